// round 12
// baseline (speedup 1.0000x reference)
#include <cuda_runtime.h>

// SpatialTransformer: affine grid + bilinear sampling.
// R8 structure (branch-free bottom-row loads + conditional top-row reuse) with
// float-pipe corner clamping (single F2I per coord, clipped floats reused as
// weights), K=16 rows/thread, and a 6-block/SM reg guard (<=42 regs).
// image: [B=16, H=256, W=256, C=64] fp32, theta: [B=16, 6], out same shape.

constexpr int B_  = 16;
constexpr int H_  = 256;
constexpr int W_  = 256;
constexpr int C_  = 64;
constexpr int OH_ = 256;
constexpr int OW_ = 256;
constexpr int K_  = 16;   // oy pixels per thread (OH_/K_ = 16 strips)

__global__ __launch_bounds__(256, 6) void stn_kernel(
    const float* __restrict__ img,
    const float* __restrict__ theta,
    float* __restrict__ out)
{
    const int gid = blockIdx.x * blockDim.x + threadIdx.x;
    const int c4  = gid & 15;          // float4 chunk (4 channels)
    const int t   = gid >> 4;          // pixel-column index
    const int ox  = t & (OW_ - 1);
    const int t2  = t >> 8;
    const int oyb = (t2 & (OH_ / K_ - 1)) * K_;
    const int b   = t2 >> 4;           // OH_/K_ = 16 -> shift 4

    const float th0 = __ldg(theta + b * 6 + 0);
    const float th1 = __ldg(theta + b * 6 + 1);
    const float th2 = __ldg(theta + b * 6 + 2);
    const float th3 = __ldg(theta + b * 6 + 3);
    const float th4 = __ldg(theta + b * 6 + 4);
    const float th5 = __ldg(theta + b * 6 + 5);

    // xt = th1*ys + (th0*xs + th2),  yt = th4*ys + (th3*xs + th5)
    const float xs = fmaf((float)ox, 2.0f / (OW_ - 1), -1.0f);
    const float xc = fmaf(th0, xs, th2);
    const float yc = fmaf(th3, xs, th5);

    // batch-folded base; per-texel float4 offset = (iy<<12) | (ix<<4)
    const float4* __restrict__ imgb =
        (const float4*)img + c4 + b * (H_ * W_ * (C_ / 4));
    float4* __restrict__ out4 =
        (float4*)out + (((b * OH_ + oyb) * OW_ + ox) * (C_ / 4) + c4);

    // carried: previous bottom-row corner values + packed (ix0,ix1,iy1) key
    float4 Pb, Pd;
    Pb = Pd = make_float4(0.f, 0.f, 0.f, 0.f);
    int pkey = -1;

#pragma unroll
    for (int k = 0; k < K_; k++) {
        const float ys = fmaf((float)(oyb + k), 2.0f / (OH_ - 1), -1.0f);
        const float x  = (fmaf(th1, ys, xc) + 1.0f) * (0.5f * (float)W_);
        const float y  = (fmaf(th4, ys, yc) + 1.0f) * (0.5f * (float)H_);

        const float xf = floorf(x), yf = floorf(y);

        // clamp in the float pipe; these ARE the clipped-corner weight floats
        const float x0f = fminf(fmaxf(xf,       0.f), (float)(W_ - 1));
        const float x1f = fminf(fmaxf(xf + 1.f, 0.f), (float)(W_ - 1));
        const float y0f = fminf(fmaxf(yf,       0.f), (float)(H_ - 1));
        const float y1f = fminf(fmaxf(yf + 1.f, 0.f), (float)(H_ - 1));

        // single F2I per corner coordinate (values are exact small integers)
        const int ix0 = (int)x0f, ix1 = (int)x1f;
        const int iy0 = (int)y0f, iy1 = (int)y1f;

        const int x0o = ix0 << 4;
        const int x1o = ix1 << 4;
        const int r1o = iy1 << 12;

        // ---- unconditional bottom-row loads: branch-free, batchable ----
        const float4 Nb = __ldg(imgb + r1o + x0o);
        const float4 Nd = __ldg(imgb + r1o + x1o);

        // ---- top-row corners: reuse prev bottom pair on exact key match ----
        const int keyT = ix0 | (ix1 << 8) | (iy0 << 16);
        float4 Na, Nc;
        if (keyT == pkey) {
            Na = Pb;
            Nc = Pd;
        } else {
            const int r0o = iy0 << 12;
            Na = __ldg(imgb + r0o + x0o);
            Nc = __ldg(imgb + r0o + x1o);
        }
        pkey = ix0 | (ix1 << 8) | (iy1 << 16);

        // weights from CLIPPED corners (matches reference)
        const float wa = (x1f - x) * (y1f - y);
        const float wb = (x1f - x) * (y - y0f);
        const float wc = (x - x0f) * (y1f - y);
        const float wd = (x - x0f) * (y - y0f);

        float4 o;
        o.x = fmaf(wa, Na.x, fmaf(wb, Nb.x, fmaf(wc, Nc.x, wd * Nd.x)));
        o.y = fmaf(wa, Na.y, fmaf(wb, Nb.y, fmaf(wc, Nc.y, wd * Nd.y)));
        o.z = fmaf(wa, Na.z, fmaf(wb, Nb.z, fmaf(wc, Nc.z, wd * Nd.z)));
        o.w = fmaf(wa, Na.w, fmaf(wb, Nb.w, fmaf(wc, Nc.w, wd * Nd.w)));

        *out4 = o;
        out4 += OW_ * (C_ / 4);

        Pb = Nb; Pd = Nd;
    }
}

extern "C" void kernel_launch(void* const* d_in, const int* in_sizes, int n_in,
                              void* d_out, int out_size)
{
    const float* img   = (const float*)d_in[0];
    const float* theta = (const float*)d_in[1];
    float* out = (float*)d_out;

    // threads = B*OW*(OH/K)*16 = 16*256*16*16 = 1,048,576 -> 4096 blocks
    const int threads = 256;
    const int blocks  = (B_ * OW_ * (OH_ / K_) * 16) / threads;

    stn_kernel<<<blocks, threads>>>(img, theta, out);
}

// round 14
// speedup vs baseline: 1.1050x; 1.1050x over previous
#include <cuda_runtime.h>

// SpatialTransformer: affine grid + bilinear sampling.
// R8 structure (branch-free bottom-row loads + conditional top-row reuse)
// + prefetch.global.L2 of row k+3's bottom-corner addresses: latency hiding
// with zero register/scoreboard cost, preserving R8's 40-reg / 65%-occ balance.
// image: [B=16, H=256, W=256, C=64] fp32, theta: [B=16, 6], out same shape.

constexpr int B_  = 16;
constexpr int H_  = 256;
constexpr int W_  = 256;
constexpr int C_  = 64;
constexpr int OH_ = 256;
constexpr int OW_ = 256;
constexpr int K_  = 8;   // oy pixels per thread (OH_/K_ = 32 strips)
constexpr int PF_ = 3;   // prefetch distance (rows)

__global__ __launch_bounds__(256) void stn_kernel(
    const float* __restrict__ img,
    const float* __restrict__ theta,
    float* __restrict__ out)
{
    const int gid = blockIdx.x * blockDim.x + threadIdx.x;
    const int c4  = gid & 15;          // float4 chunk (4 channels)
    const int t   = gid >> 4;          // pixel-column index
    const int ox  = t & (OW_ - 1);
    const int t2  = t >> 8;
    const int oyb = (t2 & (OH_ / K_ - 1)) * K_;
    const int b   = t2 >> 5;           // OH_/K_ = 32 -> shift 5

    const float th0 = __ldg(theta + b * 6 + 0);
    const float th1 = __ldg(theta + b * 6 + 1);
    const float th2 = __ldg(theta + b * 6 + 2);
    const float th3 = __ldg(theta + b * 6 + 3);
    const float th4 = __ldg(theta + b * 6 + 4);
    const float th5 = __ldg(theta + b * 6 + 5);

    // xt = th1*ys + (th0*xs + th2),  yt = th4*ys + (th3*xs + th5)
    const float xs = fmaf((float)ox, 2.0f / (OW_ - 1), -1.0f);
    const float xc = fmaf(th0, xs, th2);
    const float yc = fmaf(th3, xs, th5);

    // batch-folded base; per-texel float4 offset = (iy<<12) | (ix<<4)
    const float4* __restrict__ imgb =
        (const float4*)img + c4 + b * (H_ * W_ * (C_ / 4));
    float4* __restrict__ out4 =
        (float4*)out + (((b * OH_ + oyb) * OW_ + ox) * (C_ / 4) + c4);

    // carried state: previous bottom-row corner values + packed key
    float4 Pb, Pd;
    Pb = Pd = make_float4(0.f, 0.f, 0.f, 0.f);
    int pkey = -1;

#pragma unroll
    for (int k = 0; k < K_; k++) {
        // ---- L2 prefetch of row k+PF's bottom corners (no reg/SB cost) ----
        if (k + PF_ < K_) {
            const float ysp = fmaf((float)(oyb + k + PF_), 2.0f / (OH_ - 1), -1.0f);
            const float xp  = (fmaf(th1, ysp, xc) + 1.0f) * (0.5f * (float)W_);
            const float yp  = (fmaf(th4, ysp, yc) + 1.0f) * (0.5f * (float)H_);
            const int pix0 = min(max((int)floorf(xp),     0), W_ - 1);
            const int pix1 = min(max((int)floorf(xp) + 1, 0), W_ - 1);
            const int piy1 = min(max((int)floorf(yp) + 1, 0), H_ - 1);
            const float4* pa = imgb + (piy1 << 12) + (pix0 << 4);
            const float4* pb = imgb + (piy1 << 12) + (pix1 << 4);
            asm volatile("prefetch.global.L2 [%0];" :: "l"(pa));
            asm volatile("prefetch.global.L2 [%0];" :: "l"(pb));
        }

        const float ys = fmaf((float)(oyb + k), 2.0f / (OH_ - 1), -1.0f);
        const float x  = (fmaf(th1, ys, xc) + 1.0f) * (0.5f * (float)W_);
        const float y  = (fmaf(th4, ys, yc) + 1.0f) * (0.5f * (float)H_);

        const float xf = floorf(x), yf = floorf(y);
        const int ix0 = min(max((int)xf,     0), W_ - 1);
        const int ix1 = min(max((int)xf + 1, 0), W_ - 1);
        const int iy0 = min(max((int)yf,     0), H_ - 1);
        const int iy1 = min(max((int)yf + 1, 0), H_ - 1);

        // ---- unconditional bottom-row loads: branch-free, batchable ----
        const int x0o = ix0 << 4;
        const int x1o = ix1 << 4;
        const int r1o = iy1 << 12;
        const float4 Nb = __ldg(imgb + r1o + x0o);
        const float4 Nd = __ldg(imgb + r1o + x1o);

        // ---- top-row corners: reuse prev bottom pair on exact key match ----
        const int key = ix0 | (ix1 << 8) | (iy0 << 16);
        float4 Na, Nc;
        if (key == pkey) {
            Na = Pb;
            Nc = Pd;
        } else {
            const int r0o = iy0 << 12;
            Na = __ldg(imgb + r0o + x0o);
            Nc = __ldg(imgb + r0o + x1o);
        }
        pkey = ix0 | (ix1 << 8) | (iy1 << 16);

        // weights from CLIPPED corners cast back to float (matches reference)
        const float x0f = (float)ix0, x1f = (float)ix1;
        const float y0f = (float)iy0, y1f = (float)iy1;
        const float wa = (x1f - x) * (y1f - y);
        const float wb = (x1f - x) * (y - y0f);
        const float wc = (x - x0f) * (y1f - y);
        const float wd = (x - x0f) * (y - y0f);

        float4 o;
        o.x = fmaf(wa, Na.x, fmaf(wb, Nb.x, fmaf(wc, Nc.x, wd * Nd.x)));
        o.y = fmaf(wa, Na.y, fmaf(wb, Nb.y, fmaf(wc, Nc.y, wd * Nd.y)));
        o.z = fmaf(wa, Na.z, fmaf(wb, Nb.z, fmaf(wc, Nc.z, wd * Nd.z)));
        o.w = fmaf(wa, Na.w, fmaf(wb, Nb.w, fmaf(wc, Nc.w, wd * Nd.w)));

        *out4 = o;
        out4 += OW_ * (C_ / 4);

        Pb = Nb; Pd = Nd;
    }
}

extern "C" void kernel_launch(void* const* d_in, const int* in_sizes, int n_in,
                              void* d_out, int out_size)
{
    const float* img   = (const float*)d_in[0];
    const float* theta = (const float*)d_in[1];
    float* out = (float*)d_out;

    // threads = B*OW*(OH/K)*16 = 16*256*32*16 = 2,097,152 -> 8192 blocks
    const int threads = 256;
    const int blocks  = (B_ * OW_ * (OH_ / K_) * 16) / threads;

    stn_kernel<<<blocks, threads>>>(img, theta, out);
}